// round 3
// baseline (speedup 1.0000x reference)
#include <cuda_runtime.h>

// LS_loss fused single-kernel version.
//
// Shapes: input, img_mean : (32, 4, 512, 512) fp32, contiguous.
// 128 channels x 262144 floats (= 65536 float4 each).
//
// Per channel (N = 262144):
//   Hea = 0.5*(1+tanh(x/0.05))
//   A = sum(Hea), B1 = sum(Hea*img), S = sum(img), Q = sum(img^2)
//   c1 = B1/(A+eps), c2 = (S-B1)/(N-A+eps)
//   chan = Q - 2*(c1*B1 + c2*(S-B1)) + c1^2*A + c2^2*(N-A)
//   out  = sum_chan / (B*C*H*W)
//
// Single kernel: block partials -> g_partials; last block to arrive
// (atomic counter) finalizes the 128-channel closed form and resets the
// counter (graph-replay safe, deterministic reduction order throughout).

#define N_PER_CH    262144
#define F4_PER_CH   65536
#define BLKS_PER_CH 16
#define NBLOCKS     (128 * BLKS_PER_CH)        // 2048
#define F4_PER_BLK  (F4_PER_CH / BLKS_PER_CH)  // 4096
#define THREADS     256
#define F4_PER_THR  (F4_PER_BLK / THREADS)     // 16
#define LS_EPS      1e-4f
#define INV_EPISON  20.0f

static __device__ float4 g_partials[NBLOCKS];          // 32 KB scratch
static __device__ unsigned int g_arrive = 0;           // block arrival counter

__device__ __forceinline__ float tanh_fast(float x) {
    float y;
    asm("tanh.approx.f32 %0, %1;" : "=f"(y) : "f"(x));
    return y;
}

__device__ __forceinline__ void accum1(float x, float m,
                                       float& sH, float& sHI, float& sI, float& sI2) {
    float h = fmaf(0.5f, tanh_fast(INV_EPISON * x), 0.5f);
    sH  += h;
    sHI  = fmaf(h, m, sHI);
    sI  += m;
    sI2  = fmaf(m, m, sI2);
}

__global__ void __launch_bounds__(THREADS)
ls_loss_fused(const float4* __restrict__ inp, const float4* __restrict__ img,
              float* __restrict__ out)
{
    const int b = blockIdx.x;
    const int t = threadIdx.x;
    const long base = (long)b * F4_PER_BLK;   // block tiles one 1/16 of a channel

    float sH = 0.f, sHI = 0.f, sI = 0.f, sI2 = 0.f;

    #pragma unroll
    for (int i = 0; i < F4_PER_THR; i++) {
        const long idx = base + (long)i * THREADS + t;
        float4 x = inp[idx];
        float4 m = img[idx];
        accum1(x.x, m.x, sH, sHI, sI, sI2);
        accum1(x.y, m.y, sH, sHI, sI, sI2);
        accum1(x.z, m.z, sH, sHI, sI, sI2);
        accum1(x.w, m.w, sH, sHI, sI, sI2);
    }

    // Deterministic warp tree reduce
    #pragma unroll
    for (int o = 16; o > 0; o >>= 1) {
        sH  += __shfl_down_sync(0xFFFFFFFFu, sH,  o);
        sHI += __shfl_down_sync(0xFFFFFFFFu, sHI, o);
        sI  += __shfl_down_sync(0xFFFFFFFFu, sI,  o);
        sI2 += __shfl_down_sync(0xFFFFFFFFu, sI2, o);
    }

    __shared__ float4 sm[THREADS / 32];
    __shared__ bool   s_last;
    const int warp = t >> 5, lane = t & 31;
    if (lane == 0) sm[warp] = make_float4(sH, sHI, sI, sI2);
    __syncthreads();

    if (t == 0) {
        float4 tot = sm[0];
        #pragma unroll
        for (int w = 1; w < THREADS / 32; w++) {
            float4 v = sm[w];
            tot.x += v.x; tot.y += v.y; tot.z += v.z; tot.w += v.w;
        }
        g_partials[b] = tot;
        __threadfence();                               // publish partial before arrive
        unsigned int prev = atomicAdd(&g_arrive, 1u);
        s_last = (prev == NBLOCKS - 1);
    }
    __syncthreads();

    if (!s_last) return;

    // ---- Last block: finalize (threads 0..127 = one channel each) ----
    __threadfence();   // order partial reads after counter observation

    float chan = 0.f;
    if (t < 128) {
        float A = 0.f, B1 = 0.f, S = 0.f, Q = 0.f;
        #pragma unroll
        for (int i = 0; i < BLKS_PER_CH; i++) {
            // bypass L1 — partials written by other SMs live in L2
            const float4* p = &g_partials[t * BLKS_PER_CH + i];
            float4 v;
            asm volatile("ld.global.cg.v4.f32 {%0,%1,%2,%3}, [%4];"
                         : "=f"(v.x), "=f"(v.y), "=f"(v.z), "=f"(v.w)
                         : "l"(p));
            A += v.x; B1 += v.y; S += v.z; Q += v.w;
        }
        const float Nf = (float)N_PER_CH;
        const float s3 = Nf - A;
        const float c1 = B1 / (A + LS_EPS);
        const float c2 = (S - B1) / (s3 + LS_EPS);
        chan = Q - 2.f * (c1 * B1 + c2 * (S - B1))
             + c1 * c1 * A + c2 * c2 * s3;
    }

    #pragma unroll
    for (int o = 16; o > 0; o >>= 1)
        chan += __shfl_down_sync(0xFFFFFFFFu, chan, o);

    __shared__ float smc[4];
    if ((t & 31) == 0 && t < 128) smc[t >> 5] = chan;
    __syncthreads();

    if (t == 0) {
        out[0] = (smc[0] + smc[1] + smc[2] + smc[3])
               / (float)(32 * 4 * N_PER_CH);
        g_arrive = 0;   // reset for next graph replay
        __threadfence();
    }
}

extern "C" void kernel_launch(void* const* d_in, const int* in_sizes, int n_in,
                              void* d_out, int out_size)
{
    const float4* inp = (const float4*)d_in[0];   // 'input'
    const float4* img = (const float4*)d_in[1];   // 'img_mean'
    ls_loss_fused<<<NBLOCKS, THREADS>>>(inp, img, (float*)d_out);
}

// round 5
// speedup vs baseline: 1.0417x; 1.0417x over previous
#include <cuda_runtime.h>

// LS_loss: two-kernel version with PDL overlap (+ safe fallback launch).
//
// Shapes: input, img_mean : (32, 4, 512, 512) fp32, contiguous.
// 128 channels x 262144 floats (= 65536 float4 each).
//
// Per channel (N = 262144):
//   Hea = 0.5*(1+tanh(x/0.05))
//   A = sum(Hea), B1 = sum(Hea*img), S = sum(img), Q = sum(img^2)
//   c1 = B1/(A+eps), c2 = (S-B1)/(N-A+eps)
//   chan = Q - 2*(c1*B1 + c2*(S-B1)) + c1^2*A + c2^2*(N-A)
//   out  = sum_chan / (B*C*H*W)
//
// pass1: 2048 blocks -> per-block float4 partials (streaming __ldcs loads).
// pass2: launched with programmatic stream serialization (PDL) so its launch
//        latency hides under pass1; it grid-dep-syncs, then finalizes.
//        If cudaLaunchKernelEx is unavailable/fails, falls back to a plain
//        stream-ordered launch (grid-dep-sync is then a no-op).

#define N_PER_CH    262144
#define F4_PER_CH   65536
#define BLKS_PER_CH 16
#define NBLOCKS     (128 * BLKS_PER_CH)        // 2048
#define F4_PER_BLK  (F4_PER_CH / BLKS_PER_CH)  // 4096
#define THREADS     256
#define F4_PER_THR  (F4_PER_BLK / THREADS)     // 16
#define LS_EPS      1e-4f
#define INV_EPISON  20.0f

static __device__ float4 g_partials[NBLOCKS];   // 32 KB scratch

__device__ __forceinline__ float tanh_fast(float x) {
    float y;
    asm("tanh.approx.f32 %0, %1;" : "=f"(y) : "f"(x));
    return y;
}

__device__ __forceinline__ void accum1(float x, float m,
                                       float& sH, float& sHI, float& sI, float& sI2) {
    float h = fmaf(0.5f, tanh_fast(INV_EPISON * x), 0.5f);
    sH  += h;
    sHI  = fmaf(h, m, sHI);
    sI  += m;
    sI2  = fmaf(m, m, sI2);
}

__global__ void __launch_bounds__(THREADS)
ls_loss_pass1(const float4* __restrict__ inp, const float4* __restrict__ img)
{
    const int b = blockIdx.x;
    const int t = threadIdx.x;
    const long base = (long)b * F4_PER_BLK;   // block tiles 1/16 of one channel

    float sH = 0.f, sHI = 0.f, sI = 0.f, sI2 = 0.f;

    #pragma unroll
    for (int i = 0; i < F4_PER_THR; i++) {
        const long idx = base + (long)i * THREADS + t;
        float4 x = __ldcs(&inp[idx]);   // read-once: streaming/evict-first
        float4 m = __ldcs(&img[idx]);
        accum1(x.x, m.x, sH, sHI, sI, sI2);
        accum1(x.y, m.y, sH, sHI, sI, sI2);
        accum1(x.z, m.z, sH, sHI, sI, sI2);
        accum1(x.w, m.w, sH, sHI, sI, sI2);
    }

    // Deterministic warp tree reduce
    #pragma unroll
    for (int o = 16; o > 0; o >>= 1) {
        sH  += __shfl_down_sync(0xFFFFFFFFu, sH,  o);
        sHI += __shfl_down_sync(0xFFFFFFFFu, sHI, o);
        sI  += __shfl_down_sync(0xFFFFFFFFu, sI,  o);
        sI2 += __shfl_down_sync(0xFFFFFFFFu, sI2, o);
    }

    __shared__ float4 sm[THREADS / 32];
    const int warp = t >> 5, lane = t & 31;
    if (lane == 0) sm[warp] = make_float4(sH, sHI, sI, sI2);
    __syncthreads();

    if (t == 0) {
        float4 tot = sm[0];
        #pragma unroll
        for (int w = 1; w < THREADS / 32; w++) {
            float4 v = sm[w];
            tot.x += v.x; tot.y += v.y; tot.z += v.z; tot.w += v.w;
        }
        g_partials[b] = tot;
    }
}

__global__ void __launch_bounds__(128)
ls_loss_pass2(float* __restrict__ out)
{
    // PDL: may be scheduled while pass1 still runs. Wait for pass1
    // completion + memory visibility before reading partials.
    cudaGridDependencySynchronize();

    const int c = threadIdx.x;   // one channel per thread

    float A = 0.f, B1 = 0.f, S = 0.f, Q = 0.f;
    #pragma unroll
    for (int i = 0; i < BLKS_PER_CH; i++) {
        float4 v = g_partials[c * BLKS_PER_CH + i];
        A += v.x; B1 += v.y; S += v.z; Q += v.w;
    }

    const float Nf = (float)N_PER_CH;
    const float s3 = Nf - A;
    const float c1 = B1 / (A + LS_EPS);
    const float c2 = (S - B1) / (s3 + LS_EPS);

    float chan = Q - 2.f * (c1 * B1 + c2 * (S - B1))
               + c1 * c1 * A + c2 * c2 * s3;

    #pragma unroll
    for (int o = 16; o > 0; o >>= 1)
        chan += __shfl_down_sync(0xFFFFFFFFu, chan, o);

    __shared__ float sm[4];
    if ((c & 31) == 0) sm[c >> 5] = chan;
    __syncthreads();

    if (c == 0) {
        out[0] = (sm[0] + sm[1] + sm[2] + sm[3])
               / (float)(32 * 4 * N_PER_CH);
    }
}

extern "C" void kernel_launch(void* const* d_in, const int* in_sizes, int n_in,
                              void* d_out, int out_size)
{
    const float4* inp = (const float4*)d_in[0];   // 'input'
    const float4* img = (const float4*)d_in[1];   // 'img_mean'
    float* out = (float*)d_out;

    ls_loss_pass1<<<NBLOCKS, THREADS>>>(inp, img);

    // pass2 with programmatic dependent launch; fall back to a plain launch
    // if the Ex-launch path is rejected (behavior is then identical, minus
    // the overlap).
    cudaLaunchConfig_t cfg = {};
    cfg.gridDim  = dim3(1, 1, 1);
    cfg.blockDim = dim3(128, 1, 1);
    cfg.dynamicSmemBytes = 0;
    cfg.stream = 0;
    cudaLaunchAttribute attr[1];
    attr[0].id = cudaLaunchAttributeProgrammaticStreamSerialization;
    attr[0].val.programmaticStreamSerializationAllowed = 1;
    cfg.attrs = attr;
    cfg.numAttrs = 1;
    cudaError_t e = cudaLaunchKernelEx(&cfg, ls_loss_pass2, out);
    if (e != cudaSuccess) {
        (void)cudaGetLastError();              // clear sticky error
        ls_loss_pass2<<<1, 128>>>(out);        // ordered fallback
    }
}

// round 6
// speedup vs baseline: 1.0870x; 1.0435x over previous
#include <cuda_runtime.h>

// LS_loss: two-kernel, PDL-overlapped, MLP-pipelined mainloop.
//
// Shapes: input, img_mean : (32, 4, 512, 512) fp32, contiguous.
// 128 channels x 262144 floats (= 65536 float4 each).
//
// Per channel (N = 262144):
//   Hea = 0.5*(1+tanh(x/0.05))
//   A = sum(Hea), B1 = sum(Hea*img), S = sum(img), Q = sum(img^2)
//   c1 = B1/(A+eps), c2 = (S-B1)/(N-A+eps)
//   chan = Q - 2*(c1*B1 + c2*(S-B1)) + c1^2*A + c2^2*(N-A)
//   out  = sum_chan / (B*C*H*W)
//
// pass1: 2048 blocks; each thread processes 16 float4-pairs in 4 groups of 4,
//        with all 8 loads of a group issued before any compute (MLP_p1~8).
// pass2: PDL-launched finalize (launch latency hides under pass1).

#define N_PER_CH    262144
#define F4_PER_CH   65536
#define BLKS_PER_CH 16
#define NBLOCKS     (128 * BLKS_PER_CH)        // 2048
#define F4_PER_BLK  (F4_PER_CH / BLKS_PER_CH)  // 4096
#define THREADS     256
#define F4_PER_THR  (F4_PER_BLK / THREADS)     // 16
#define GRP         4                          // pairs batched per group
#define NGRP        (F4_PER_THR / GRP)         // 4
#define LS_EPS      1e-4f
#define INV_EPISON  20.0f

static __device__ float4 g_partials[NBLOCKS];   // 32 KB scratch

__device__ __forceinline__ float tanh_fast(float x) {
    float y;
    asm("tanh.approx.f32 %0, %1;" : "=f"(y) : "f"(x));
    return y;
}

__device__ __forceinline__ void accum1(float x, float m,
                                       float& sH, float& sHI, float& sI, float& sI2) {
    float h = fmaf(0.5f, tanh_fast(INV_EPISON * x), 0.5f);
    sH  += h;
    sHI  = fmaf(h, m, sHI);
    sI  += m;
    sI2  = fmaf(m, m, sI2);
}

__global__ void __launch_bounds__(THREADS, 5)
ls_loss_pass1(const float4* __restrict__ inp, const float4* __restrict__ img)
{
    const int b = blockIdx.x;
    const int t = threadIdx.x;
    const long base = (long)b * F4_PER_BLK + t;  // block tiles 1/16 of one channel

    float sH = 0.f, sHI = 0.f, sI = 0.f, sI2 = 0.f;

    #pragma unroll
    for (int g = 0; g < NGRP; g++) {
        float4 x[GRP], m[GRP];
        // Front-batch all 8 loads of this group: MLP_p1 ~ 8 per thread.
        #pragma unroll
        for (int j = 0; j < GRP; j++) {
            const long idx = base + (long)(g * GRP + j) * THREADS;
            x[j] = __ldcs(&inp[idx]);
            m[j] = __ldcs(&img[idx]);
        }
        #pragma unroll
        for (int j = 0; j < GRP; j++) {
            accum1(x[j].x, m[j].x, sH, sHI, sI, sI2);
            accum1(x[j].y, m[j].y, sH, sHI, sI, sI2);
            accum1(x[j].z, m[j].z, sH, sHI, sI, sI2);
            accum1(x[j].w, m[j].w, sH, sHI, sI, sI2);
        }
    }

    // Deterministic warp tree reduce
    #pragma unroll
    for (int o = 16; o > 0; o >>= 1) {
        sH  += __shfl_down_sync(0xFFFFFFFFu, sH,  o);
        sHI += __shfl_down_sync(0xFFFFFFFFu, sHI, o);
        sI  += __shfl_down_sync(0xFFFFFFFFu, sI,  o);
        sI2 += __shfl_down_sync(0xFFFFFFFFu, sI2, o);
    }

    __shared__ float4 sm[THREADS / 32];
    const int warp = t >> 5, lane = t & 31;
    if (lane == 0) sm[warp] = make_float4(sH, sHI, sI, sI2);
    __syncthreads();

    if (t == 0) {
        float4 tot = sm[0];
        #pragma unroll
        for (int w = 1; w < THREADS / 32; w++) {
            float4 v = sm[w];
            tot.x += v.x; tot.y += v.y; tot.z += v.z; tot.w += v.w;
        }
        g_partials[b] = tot;
    }
}

__global__ void __launch_bounds__(128)
ls_loss_pass2(float* __restrict__ out)
{
    // PDL: may be scheduled while pass1 still runs; wait for completion +
    // visibility before reading partials. No-op if launched plainly.
    cudaGridDependencySynchronize();

    const int c = threadIdx.x;   // one channel per thread

    float A = 0.f, B1 = 0.f, S = 0.f, Q = 0.f;
    #pragma unroll
    for (int i = 0; i < BLKS_PER_CH; i++) {
        float4 v = g_partials[c * BLKS_PER_CH + i];
        A += v.x; B1 += v.y; S += v.z; Q += v.w;
    }

    const float Nf = (float)N_PER_CH;
    const float s3 = Nf - A;
    const float c1 = B1 / (A + LS_EPS);
    const float c2 = (S - B1) / (s3 + LS_EPS);

    float chan = Q - 2.f * (c1 * B1 + c2 * (S - B1))
               + c1 * c1 * A + c2 * c2 * s3;

    #pragma unroll
    for (int o = 16; o > 0; o >>= 1)
        chan += __shfl_down_sync(0xFFFFFFFFu, chan, o);

    __shared__ float sm[4];
    if ((c & 31) == 0) sm[c >> 5] = chan;
    __syncthreads();

    if (c == 0) {
        out[0] = (sm[0] + sm[1] + sm[2] + sm[3])
               / (float)(32 * 4 * N_PER_CH);
    }
}

extern "C" void kernel_launch(void* const* d_in, const int* in_sizes, int n_in,
                              void* d_out, int out_size)
{
    const float4* inp = (const float4*)d_in[0];   // 'input'
    const float4* img = (const float4*)d_in[1];   // 'img_mean'
    float* out = (float*)d_out;

    ls_loss_pass1<<<NBLOCKS, THREADS>>>(inp, img);

    // pass2 via PDL; plain ordered launch as fallback.
    cudaLaunchConfig_t cfg = {};
    cfg.gridDim  = dim3(1, 1, 1);
    cfg.blockDim = dim3(128, 1, 1);
    cfg.dynamicSmemBytes = 0;
    cfg.stream = 0;
    cudaLaunchAttribute attr[1];
    attr[0].id = cudaLaunchAttributeProgrammaticStreamSerialization;
    attr[0].val.programmaticStreamSerializationAllowed = 1;
    cfg.attrs = attr;
    cfg.numAttrs = 1;
    cudaError_t e = cudaLaunchKernelEx(&cfg, ls_loss_pass2, out);
    if (e != cudaSuccess) {
        (void)cudaGetLastError();
        ls_loss_pass2<<<1, 128>>>(out);
    }
}